// round 13
// baseline (speedup 1.0000x reference)
#include <cuda_runtime.h>

#define WARPS_PER_BLOCK 8
#define PAIRS 8
#define ROWS_PER_WARP (2 * PAIRS)                           // 16
#define ROWS_PER_BLOCK (WARPS_PER_BLOCK * ROWS_PER_WARP)    // 128

__device__ __forceinline__ float dot4(float4 a, float4 b) {
    return a.x*b.x + a.y*b.y + a.z*b.z + a.w*b.w;
}

// 8-value packed warp reduction, 9 SHFL. After return, every lane in 4-lane
// group g (= lane>>2) holds the warp-total of slot g.
__device__ __forceinline__ float oct_reduce(const float v[8], int lane)
{
    const unsigned F = 0xFFFFFFFFu;
    const bool lo16 = (lane & 16) == 0;
    float s0, s1, s2, s3;
    {
        float e0 = lo16 ? v[4] : v[0];
        float e1 = lo16 ? v[5] : v[1];
        float e2 = lo16 ? v[6] : v[2];
        float e3 = lo16 ? v[7] : v[3];
        float r0 = __shfl_xor_sync(F, e0, 16);
        float r1 = __shfl_xor_sync(F, e1, 16);
        float r2 = __shfl_xor_sync(F, e2, 16);
        float r3 = __shfl_xor_sync(F, e3, 16);
        s0 = (lo16 ? v[0] : v[4]) + r0;
        s1 = (lo16 ? v[1] : v[5]) + r1;
        s2 = (lo16 ? v[2] : v[6]) + r2;
        s3 = (lo16 ? v[3] : v[7]) + r3;
    }
    const bool lo8 = (lane & 8) == 0;
    float u0, u1;
    {
        float e0 = lo8 ? s2 : s0;
        float e1 = lo8 ? s3 : s1;
        float r0 = __shfl_xor_sync(F, e0, 8);
        float r1 = __shfl_xor_sync(F, e1, 8);
        u0 = (lo8 ? s0 : s2) + r0;
        u1 = (lo8 ? s1 : s3) + r1;
    }
    const bool lo4 = (lane & 4) == 0;
    float t;
    {
        float e = lo4 ? u1 : u0;
        float r = __shfl_xor_sync(F, e, 4);
        t = (lo4 ? u0 : u1) + r;
    }
    t += __shfl_xor_sync(F, t, 2);
    t += __shfl_xor_sync(F, t, 1);
    return t;
}

// 4-value reduction (halo only). PD valid on lane 0; PS broadcast.
__device__ __forceinline__ void quad_reduce(float pd, float ps, float q0, float q1,
                                            int lane, float& PD, float& PS)
{
    const unsigned F = 0xFFFFFFFFu;
    const bool lo16 = (lane & 16) == 0;
    float a  = lo16 ? q0 : pd;
    float b  = lo16 ? q1 : ps;
    float ra = __shfl_xor_sync(F, a, 16);
    float rb = __shfl_xor_sync(F, b, 16);
    float u  = (lo16 ? pd : q0) + ra;
    float v  = (lo16 ? ps : q1) + rb;
    const bool lo8 = (lane & 8) == 0;
    float c  = lo8 ? v : u;
    float rc = __shfl_xor_sync(F, c, 8);
    float s  = (lo8 ? u : v) + rc;
    s += __shfl_xor_sync(F, s, 4);
    s += __shfl_xor_sync(F, s, 2);
    s += __shfl_xor_sync(F, s, 1);
    PD = s;                          // lane 0
    PS = __shfl_sync(F, s, 8);
}

__global__ __launch_bounds__(WARPS_PER_BLOCK * 32)
void smf_kernel(const float* __restrict__ X,
                const float* __restrict__ theta,
                const float* __restrict__ f_bias,
                const float* __restrict__ xi,
                const float* __restrict__ g_bias,
                float* __restrict__ out,
                int N)
{
    __shared__ float4 xis[64];                      // xi: 2 x 128 floats
    __shared__ float2 Vnext[WARPS_PER_BLOCK + 1];   // [w]=warp w first-row V, [8]=halo
    __shared__ float2 obuf[WARPS_PER_BLOCK][ROWS_PER_WARP];

    const unsigned F = 0xFFFFFFFFu;
    const int warp = threadIdx.x >> 5;
    const int lane = threadIdx.x & 31;
    const int base = (blockIdx.x * WARPS_PER_BLOCK + warp) * ROWS_PER_WARP;

    const float4* __restrict__ X4  = reinterpret_cast<const float4*>(X);
    const float4* __restrict__ T4  = reinterpret_cast<const float4*>(theta);
    const float4* __restrict__ XI4 = reinterpret_cast<const float4*>(xi);

    if (threadIdx.x < 64)
        xis[threadIdx.x] = XI4[threadIdx.x];

    const float gb0 = g_bias[0];
    const float gb1 = g_bias[1];

    // Live pair state: rows 2p, 2p+1 of this warp.
    float4 x_a = __ldcs(X4 + (size_t)base * 32 + lane);
    float4 x_b = __ldcs(X4 + (size_t)(base + 1) * 32 + lane);
    float4 t0  = __ldcs(T4 + (size_t)base * 32 + lane);
    float4 t1  = __ldcs(T4 + (size_t)(base + 1) * 32 + lane);
    float4 t2  = __ldcs(T4 + (size_t)(base + 2) * 32 + lane);
    float fb_a = __ldg(f_bias + base);
    float fb_b = __ldg(f_bias + base + 1);

    __syncthreads();   // xis visible

    const int g  = lane >> 2;
    const int hi = lane & 16;

    float wdb = 0.0f, wsb = 0.0f, v0b = 0.0f, v1b = 0.0f;   // carry (lane 16)

    #pragma unroll
    for (int p = 0; p < PAIRS; p++) {
        const int ra = base + 2 * p;

        int ic = ra + 2;
        if (ic >= N) ic -= N;                    // only last warp, p==7
        const float fb_c = __ldg(f_bias + ic);

        const float4 w0 = xis[lane];
        const float4 w1 = xis[32 + lane];

        float v[8];
        v[0] = dot4(x_a, t0);    // pd_a
        v[1] = dot4(x_a, t1);    // ps_a
        v[2] = dot4(x_a, w0);    // q0_a
        v[3] = dot4(x_a, w1);    // q1_a
        v[4] = dot4(x_b, t1);    // pd_b
        v[5] = dot4(x_b, t2);    // ps_b
        v[6] = dot4(x_b, w0);    // q0_b
        v[7] = dot4(x_b, w1);    // q1_b

        // Per-lane bias selection BEFORE fb_a/fb_b are overwritten
        float bias;
        if (g & 2)        bias = (g & 1) ? gb1 : gb0;   // slots 2,3,6,7
        else if (g == 0)  bias = fb_a;                  // pd_a
        else if (g == 5)  bias = fb_c;                  // ps_b
        else              bias = fb_b;                  // ps_a (g==1), pd_b (g==4)

        // Rotate + prefetch next pair DIRECTLY into dead registers.
        // After the dots: x_a, x_b, t1 are dead; t2 renames to next t0.
        fb_a = fb_c;
        t0 = t2;
        if (p < PAIRS - 1) {
            x_a = __ldcs(X4 + (size_t)(ra + 2) * 32 + lane);
            x_b = __ldcs(X4 + (size_t)(ra + 3) * 32 + lane);
            t1  = __ldcs(T4 + (size_t)(ra + 3) * 32 + lane);
            int i4 = ra + 4;
            if (i4 >= N) i4 -= N;
            t2  = __ldcs(T4 + (size_t)i4 * 32 + lane);
            fb_b = __ldg(f_bias + (ra + 3));
        }

        // Long SHFL chain hides the prefetch latency
        const float s = oct_reduce(v, lane);
        const float w = fmaxf(s + bias, 0.0f);

        // Distribute: lanes<16 get a-row values, lanes>=16 get b-row values
        const float a1 = __shfl_sync(F, w,  4 + hi);    // ws
        const float a2 = __shfl_sync(F, w,  8 + hi);    // v0
        const float a3 = __shfl_sync(F, w, 12 + hi);    // v1
        // Cross: lane0 <- b-row v0/v1 ; lane16 <- a-row v0/v1
        const float b2 = __shfl_sync(F, a2, hi ^ 16);
        const float b3 = __shfl_sync(F, a3, hi ^ 16);

        if (lane == 0) {
            if (p == 0)
                Vnext[warp] = make_float2(a2, a3);       // V[base]
            // row ra: wd_a*V_a + ws_a*V_b
            obuf[warp][2 * p] = make_float2(w * a2 + a1 * b2,
                                            w * a3 + a1 * b3);
        }
        if (lane == 16) {
            if (p > 0) {
                // previous pair's b-row: wd_b*V_b + ws_b*V_a(current pair)
                obuf[warp][2 * p - 1] = make_float2(wdb * v0b + wsb * b2,
                                                    wdb * v1b + wsb * b3);
            }
            wdb = w; wsb = a1; v0b = a2; v1b = a3;
        }
    }

    // Halo V for the block's last warp
    if (warp == WARPS_PER_BLOCK - 1) {
        int h = base + ROWS_PER_WARP;
        if (h >= N) h -= N;
        const float4 xh = __ldcs(X4 + (size_t)h * 32 + lane);
        float h0 = dot4(xh, xis[lane]);
        float h1 = dot4(xh, xis[32 + lane]);
        float H0, H1;
        quad_reduce(h0, h1, 0.0f, 0.0f, lane, H0, H1);
        if (lane == 0)
            Vnext[WARPS_PER_BLOCK] = make_float2(fmaxf(H0 + gb0, 0.0f),
                                                 fmaxf(H1 + gb1, 0.0f));
    }
    __syncthreads();

    // Emit this warp's final row (pair 7 b-row) from lane 16
    if (lane == 16) {
        const float2 vn = Vnext[warp + 1];
        obuf[warp][ROWS_PER_WARP - 1] = make_float2(wdb * v0b + wsb * vn.x,
                                                    wdb * v1b + wsb * vn.y);
    }
    __syncwarp();

    // Coalesced store: 16 lanes write the warp's 16 float2 results (128B)
    if (lane < ROWS_PER_WARP)
        reinterpret_cast<float2*>(out)[base + lane] = obuf[warp][lane];
}

extern "C" void kernel_launch(void* const* d_in, const int* in_sizes, int n_in,
                              void* d_out, int out_size)
{
    const float* X      = (const float*)d_in[0];
    const float* theta  = (const float*)d_in[1];
    const float* f_bias = (const float*)d_in[2];
    const float* xi     = (const float*)d_in[3];
    const float* g_bias = (const float*)d_in[4];
    float* out = (float*)d_out;

    const int N = in_sizes[2];                   // f_bias has N elements
    const int blocks = N / ROWS_PER_BLOCK;       // 524288 / 128 = 4096

    smf_kernel<<<blocks, WARPS_PER_BLOCK * 32>>>(X, theta, f_bias, xi, g_bias, out, N);
}

// round 14
// speedup vs baseline: 1.1030x; 1.1030x over previous
#include <cuda_runtime.h>
#include <cstdint>

#define THREADS 128
#define ROWS 128                         // rows per block (== THREADS)
#define UNITS 8                          // 16B units per row per chunk
#define NCHUNK 4                         // D=128 floats / 32 per chunk
#define STAGE_UNITS (2 * ROWS * UNITS)   // X rows then theta rows: 2048 float4
#define STAGE_BYTES (STAGE_UNITS * 16)   // 32768 B

#define XI_OFF   (2 * STAGE_BYTES)            // 64 float4  (1KB)
#define TH_OFF   (XI_OFF + 1024)              // theta halo row: 32 float4 (512B)
#define V_OFF    (TH_OFF + 512)               // V exchange: 129 float2
#define SMEM_TOTAL (V_OFF + 129 * 8 + 8)

__device__ __forceinline__ void cp_async16(uint32_t dst_smem, const void* src) {
    asm volatile("cp.async.cg.shared.global [%0], [%1], 16;\n"
                 :: "r"(dst_smem), "l"(src));
}
__device__ __forceinline__ void cp_commit() {
    asm volatile("cp.async.commit_group;\n");
}
template <int NN>
__device__ __forceinline__ void cp_wait() {
    asm volatile("cp.async.wait_group %0;\n" :: "n"(NN));
}

__device__ __forceinline__ float dot4(float4 a, float4 b) {
    return a.x*b.x + a.y*b.y + a.z*b.z + a.w*b.w;
}
__device__ __forceinline__ void acc4(float& a, float4 x, float4 y) {
    a = fmaf(x.x, y.x, a);
    a = fmaf(x.y, y.y, a);
    a = fmaf(x.z, y.z, a);
    a = fmaf(x.w, y.w, a);
}

__global__ __launch_bounds__(THREADS)
void smf_kernel(const float* __restrict__ X,
                const float* __restrict__ theta,
                const float* __restrict__ f_bias,
                const float* __restrict__ xi,
                const float* __restrict__ g_bias,
                float* __restrict__ out,
                int N)
{
    extern __shared__ char smem[];
    float4* __restrict__ buf = reinterpret_cast<float4*>(smem);
    float4* __restrict__ xis = reinterpret_cast<float4*>(smem + XI_OFF);
    float4* __restrict__ thh = reinterpret_cast<float4*>(smem + TH_OFF);
    float2* __restrict__ vsh = reinterpret_cast<float2*>(smem + V_OFF);

    const int tid  = threadIdx.x;
    const int base = blockIdx.x * ROWS;

    const float4* __restrict__ X4  = reinterpret_cast<const float4*>(X);
    const float4* __restrict__ T4  = reinterpret_cast<const float4*>(theta);
    const float4* __restrict__ XI4 = reinterpret_cast<const float4*>(xi);

    const uint32_t sb = (uint32_t)__cvta_generic_to_shared(smem);

    int hrow = base + ROWS;
    if (hrow >= N) hrow -= N;

    // One-time smem fills (visible after first in-loop __syncthreads)
    if (tid < 64) {
        xis[tid] = XI4[tid];
    } else if (tid < 96) {
        thh[tid - 64] = T4[(size_t)hrow * 32 + (tid - 64)];
    }

    // X-halo loads issued early; reduced at the very end (warp 0 only)
    float4 xh, hw0, hw1;
    if (tid < 32) {
        xh  = __ldg(X4 + (size_t)hrow * 32 + tid);
        hw0 = __ldg(XI4 + tid);
        hw1 = __ldg(XI4 + 32 + tid);
    }

    // Per-thread invariant issue geometry: idx = tid + 128k -> row = r0+16k,
    // u const, and (row & 7) == (r0 & 7) so the swizzle XOR is constant.
    const int r0 = tid >> 3;        // 0..15
    const int u  = tid & 7;
    const int su = u ^ (r0 & 7);

    auto issue = [&](int c, int s) {
        const float4* xsrc = X4 + (size_t)(base + r0) * 32 + c * UNITS + u;
        const float4* tsrc = T4 + (size_t)(base + r0) * 32 + c * UNITS + u;
        const uint32_t xd = sb + (uint32_t)s * STAGE_BYTES + (uint32_t)(r0 * UNITS + su) * 16;
        const uint32_t td = xd + (uint32_t)(ROWS * UNITS) * 16;
        #pragma unroll
        for (int k = 0; k < 8; k++) {
            cp_async16(xd + (uint32_t)k * 2048, xsrc + (size_t)k * 512);
            cp_async16(td + (uint32_t)k * 2048, tsrc + (size_t)k * 512);
        }
        cp_commit();
    };

    issue(0, 0);
    issue(1, 1);

    float pd = 0.0f, ps = 0.0f, q0 = 0.0f, q1 = 0.0f;

    const int mx = tid & 7;              // swizzle xor for x / theta-diag rows
    #pragma unroll
    for (int c = 0; c < NCHUNK; c++) {
        if (c < NCHUNK - 1) cp_wait<1>(); else cp_wait<0>();
        __syncthreads();

        const float4* __restrict__ st = buf + (c & 1) * STAGE_UNITS;
        const float4* __restrict__ xrow = st + tid * UNITS;
        const float4* __restrict__ trow = st + (ROWS + tid) * UNITS;

        const float4* sptr;
        int sxor;
        if (tid < ROWS - 1) { sptr = st + (ROWS + tid + 1) * UNITS; sxor = (tid + 1) & 7; }
        else                { sptr = thh + c * UNITS;               sxor = 0; }

        #pragma unroll
        for (int uu = 0; uu < UNITS; uu++) {
            float4 xv = xrow[uu ^ mx];
            float4 td = trow[uu ^ mx];
            float4 ts = sptr[uu ^ sxor];
            float4 w0 = xis[c * UNITS + uu];         // broadcast
            float4 w1 = xis[32 + c * UNITS + uu];    // broadcast
            acc4(pd, xv, td);
            acc4(ps, xv, ts);
            acc4(q0, xv, w0);
            acc4(q1, xv, w1);
        }

        __syncthreads();
        if (c + 2 < NCHUNK) issue(c + 2, c & 1);
    }

    // ---- Epilogue ----
    const float gb0 = g_bias[0];
    const float gb1 = g_bias[1];

    const int i = base + tid;
    int in = i + 1;
    if (in >= N) in -= N;

    const float wd = fmaxf(pd + __ldg(f_bias + i),  0.0f);
    const float ws = fmaxf(ps + __ldg(f_bias + in), 0.0f);
    const float v0 = fmaxf(q0 + gb0, 0.0f);
    const float v1 = fmaxf(q1 + gb1, 0.0f);
    vsh[tid] = make_float2(v0, v1);

    // Halo V (warp 0): loads were issued at kernel start
    if (tid < 32) {
        float h0 = dot4(xh, hw0);
        float h1 = dot4(xh, hw1);
        #pragma unroll
        for (int o = 16; o > 0; o >>= 1) {
            h0 += __shfl_xor_sync(0xFFFFFFFFu, h0, o);
            h1 += __shfl_xor_sync(0xFFFFFFFFu, h1, o);
        }
        if (tid == 0)
            vsh[ROWS] = make_float2(fmaxf(h0 + gb0, 0.0f), fmaxf(h1 + gb1, 0.0f));
    }
    __syncthreads();

    const float2 vn = vsh[tid + 1];
    float2 o;
    o.x = wd * v0 + ws * vn.x;
    o.y = wd * v1 + ws * vn.y;
    reinterpret_cast<float2*>(out)[i] = o;
}

extern "C" void kernel_launch(void* const* d_in, const int* in_sizes, int n_in,
                              void* d_out, int out_size)
{
    const float* X      = (const float*)d_in[0];
    const float* theta  = (const float*)d_in[1];
    const float* f_bias = (const float*)d_in[2];
    const float* xi     = (const float*)d_in[3];
    const float* g_bias = (const float*)d_in[4];
    float* out = (float*)d_out;

    const int N = in_sizes[2];            // f_bias has N elements
    const int blocks = N / ROWS;          // 524288 / 128 = 4096

    cudaFuncSetAttribute(smf_kernel,
                         cudaFuncAttributeMaxDynamicSharedMemorySize,
                         SMEM_TOTAL);

    smf_kernel<<<blocks, THREADS, SMEM_TOTAL>>>(X, theta, f_bias, xi, g_bias, out, N);
}